// round 13
// baseline (speedup 1.0000x reference)
#include <cuda_runtime.h>
#include <math.h>

#define BB 2
#define NN 1024
#define MM 1024
#define DD 512
#define HH 8
#define DHh 64
#define DEPTHL 4
#define VV 32000
#define FF 2048
#define MN (MM + NN)
#define QKVW 1536

// ---------------- scratch (static device globals; no allocation) ----------------
__device__ float g_x[BB * NN * DD];       // residual stream, exact fp32
__device__ float g_xt[BB * NN * DD];      // tf32-rounded shadow of x (GEMM A input)
__device__ float g_memt[DEPTHL * BB * MM * DD];  // tf32-rounded copy of mems
__device__ float g_qkv[BB * NN * QKVW];   // rounded
__device__ float g_memkv[BB * MM * 2 * DD];      // rounded
__device__ float g_att[BB * NN * DD];     // rounded
__device__ float g_h1[BB * NN * FF];      // rounded
__device__ float g_xn[BB * NN * DD];      // rounded
__device__ float g_pe[NN * DD];           // rounded
__device__ float g_pos_all[DEPTHL * NN * DHh];   // rounded
__device__ float g_posT_all[DEPTHL * DHh * NN];
__device__ float g_P[BB * HH * NN * NN];
__device__ float g_em_all[DEPTHL * BB * MM];
__device__ float g_aux[BB];

// ---------------- tf32 helpers ----------------
__device__ __forceinline__ unsigned f2tf32(float x) {
    unsigned u;
    asm("cvt.rna.tf32.f32 %0, %1;" : "=r"(u) : "f"(x));
    return u;
}
__device__ __forceinline__ float roundtf(float x) { return __uint_as_float(f2tf32(x)); }

__device__ __forceinline__ void mma_tf32(float* c, const unsigned* a, const unsigned* b) {
    asm volatile(
        "mma.sync.aligned.m16n8k8.row.col.f32.tf32.tf32.f32 "
        "{%0,%1,%2,%3}, {%4,%5,%6,%7}, {%8,%9}, {%0,%1,%2,%3};\n"
        : "+f"(c[0]), "+f"(c[1]), "+f"(c[2]), "+f"(c[3])
        : "r"(a[0]), "r"(a[1]), "r"(a[2]), "r"(a[3]), "r"(b[0]), "r"(b[1]));
}

__device__ __forceinline__ void ldsm_x4(unsigned* r, unsigned saddr) {
    asm volatile("ldmatrix.sync.aligned.m8n8.x4.shared.b16 {%0,%1,%2,%3}, [%4];"
        : "=r"(r[0]), "=r"(r[1]), "=r"(r[2]), "=r"(r[3]) : "r"(saddr));
}

__device__ __forceinline__ void cp16(unsigned dst, const float* src, unsigned sz) {
    asm volatile("cp.async.ca.shared.global [%0], [%1], 16, %2;"
        :: "r"(dst), "l"(src), "r"(sz));
}
__device__ __forceinline__ void cp_commit() { asm volatile("cp.async.commit_group;"); }
template<int Nn> __device__ __forceinline__ void cp_wait() {
    asm volatile("cp.async.wait_group %0;" :: "n"(Nn));
}

// ---------------- tf32 GEMM: cp.async for BOTH operands (pre-rounded in gmem) ----
// C[M,N] = act(A[M,K] @ B[K,N] + bias) + res.  TMI: M-tile = 32*TMI, N-tile 128.
// smem: As[2][TM][36] + Bs[2][32][136]. Global A and B MUST hold tf32 values.
// Ct (optional): second output, tf32-rounded (same layout/strides as C).
// __launch_bounds__(256,3): cap regs at 84 -> 3 CTAs/SM (24 warps) for latency hiding.
template<int TMI>
__global__ void __launch_bounds__(256, 3) gemm_tc_kernel(
    const float* __restrict__ A, const float* __restrict__ Bw,
    const float* __restrict__ Bw2, int nsplit, int ldb1, int ldb2,
    const float* __restrict__ bias, const float* __restrict__ bias2,
    const float* __restrict__ res, float* __restrict__ C, float* __restrict__ Ct,
    int M, int N, int K, int lda,
    long sA, long sA2, long sB2, long sBias2, long sC, long sC2,
    int zH, int doGelu, int doRound)
{
    constexpr int TM = 32 * TMI;
    constexpr int ASTG = TM * 36;
    constexpr int BSTG = 32 * 136;
    extern __shared__ unsigned smu[];

    int zb = blockIdx.z / zH, zh = blockIdx.z % zH;
    A += (long)zb * sA + (long)zh * sA2;
    Bw += (long)zh * sB2;
    if (bias) bias += (long)zh * sBias2;
    C += (long)zb * sC + (long)zh * sC2;
    if (Ct) Ct += (long)zb * sC + (long)zh * sC2;
    const float* resb = res ? (res + (long)zb * sC + (long)zh * sC2) : (const float*)0;

    const int tid = threadIdx.x;
    const int lane = tid & 31;
    const int warp = tid >> 5;
    const int m0 = blockIdx.y * TM;
    const int n0 = blockIdx.x * 128;
    const int wm = (warp >> 2) * (TM / 2);
    const int wn = (warp & 3) * 32;
    const int g = lane >> 2;
    const int tg = lane & 3;

    const float* Bu; const float* biasu; int ldb, nloc;
    if (n0 >= nsplit) { Bu = Bw2; biasu = bias2; ldb = ldb2; nloc = n0 - nsplit; }
    else             { Bu = Bw;  biasu = bias;  ldb = ldb1; nloc = n0; }

    const int arow = tid >> 3;
    const int acol = (tid & 7) << 2;
    const int brow = tid >> 5;
    const int bcol = (tid & 31) << 2;

    const float* Aptr = A + (long)(m0 + arow) * lda + acol;
    const float* Bbase = Bu + nloc + bcol;
    const bool bOK = (n0 + bcol + 4) <= N;
    const unsigned bsz = bOK ? 16u : 0u;

    float acc[TMI][4][4];
#pragma unroll
    for (int mi = 0; mi < TMI; mi++)
#pragma unroll
        for (int ni = 0; ni < 4; ni++)
#pragma unroll
            for (int r = 0; r < 4; r++) acc[mi][ni][r] = 0.f;

    const int chunks = K >> 5;

    unsigned smem_b = (unsigned)__cvta_generic_to_shared(smu);
    const unsigned aDst = smem_b + (unsigned)(arow * 36 + acol) * 4u;
    const unsigned bDst = smem_b + (unsigned)(2 * ASTG) * 4u
                                 + (unsigned)(brow * 136 + bcol) * 4u;
    const unsigned aFragBase = smem_b + (unsigned)((wm + (lane & 15)) * 36) * 4u
                                      + (unsigned)(lane >> 4) * 16u;

    // prologue: chunk 0 into buf 0
    {
#pragma unroll
        for (int i = 0; i < TMI; i++)
            cp16(aDst + (unsigned)(i * 32 * 36) * 4u, Aptr + (long)i * 32 * lda, 16u);
#pragma unroll
        for (int i = 0; i < 4; i++)
            cp16(bDst + (unsigned)(i * 8 * 136) * 4u,
                 bOK ? Bbase + (long)(brow + i * 8) * ldb : Bu, bsz);
        cp_commit();
        cp_wait<0>();
        __syncthreads();
    }

    for (int c = 0; c < chunks; c++) {
        const int buf = c & 1;
        const unsigned aBufBase = aFragBase + (unsigned)buf * (ASTG * 4);
        const unsigned* Bs = smu + 2 * ASTG + buf * BSTG;
        const bool more = (c + 1 < chunks);

        if (more) {
            int k0 = (c + 1) << 5;
            unsigned ad = aDst + (unsigned)((buf ^ 1) * ASTG) * 4u;
#pragma unroll
            for (int i = 0; i < TMI; i++)
                cp16(ad + (unsigned)(i * 32 * 36) * 4u, Aptr + (long)i * 32 * lda + k0, 16u);
            unsigned bd = bDst + (unsigned)((buf ^ 1) * BSTG) * 4u;
#pragma unroll
            for (int i = 0; i < 4; i++)
                cp16(bd + (unsigned)(i * 8 * 136) * 4u,
                     bOK ? Bbase + (long)(k0 + brow + i * 8) * ldb : Bu, bsz);
            cp_commit();
        }

#pragma unroll
        for (int kk = 0; kk < 4; kk++) {
            int ko = kk << 3;
            unsigned af[TMI][4];
#pragma unroll
            for (int mi = 0; mi < TMI; mi++)
                ldsm_x4(af[mi], aBufBase + (unsigned)(mi * (16 * 36 * 4) + kk * 32));
            unsigned bf[4][2];
#pragma unroll
            for (int ni = 0; ni < 4; ni++) {
                int cN = wn + ni * 8 + g;
                bf[ni][0] = Bs[(ko + tg) * 136 + cN];
                bf[ni][1] = Bs[(ko + tg + 4) * 136 + cN];
            }
#pragma unroll
            for (int mi = 0; mi < TMI; mi++)
#pragma unroll
                for (int ni = 0; ni < 4; ni++)
                    mma_tf32(acc[mi][ni], af[mi], bf[ni]);
        }

        cp_wait<0>();
        __syncthreads();
    }

    const int biasOff = nloc - n0;
#pragma unroll
    for (int mi = 0; mi < TMI; mi++) {
        int gm0 = m0 + wm + mi * 16 + g;
#pragma unroll
        for (int ni = 0; ni < 4; ni++) {
            int gn = n0 + wn + ni * 8 + 2 * tg;
            if (gn >= N) continue;
            float bsum0 = biasu ? biasu[gn + biasOff] : 0.f;
            float bsum1 = biasu ? biasu[gn + biasOff + 1] : 0.f;
#pragma unroll
            for (int half = 0; half < 2; half++) {
                int gm = gm0 + half * 8;
                float v0 = acc[mi][ni][half * 2 + 0] + bsum0;
                float v1 = acc[mi][ni][half * 2 + 1] + bsum1;
                if (doGelu) {
                    v0 = 0.5f * v0 * (1.0f + erff(v0 * 0.7071067811865476f));
                    v1 = 0.5f * v1 * (1.0f + erff(v1 * 0.7071067811865476f));
                }
                if (resb) {
                    const float2 r2 = *(const float2*)(resb + (long)gm * N + gn);
                    v0 += r2.x; v1 += r2.y;
                }
                if (doRound) { v0 = roundtf(v0); v1 = roundtf(v1); }
                *(float2*)(C + (long)gm * N + gn) = make_float2(v0, v1);
                if (Ct)
                    *(float2*)(Ct + (long)gm * N + gn) =
                        make_float2(roundtf(v0), roundtf(v1));
            }
        }
    }
}

// ---------------- tf32 rounding kernels ----------------
__global__ void cvt4_kernel(float4* __restrict__ p, int n4)
{
    int i = blockIdx.x * blockDim.x + threadIdx.x;
    if (i < n4) {
        float4 v = p[i];
        v.x = roundtf(v.x); v.y = roundtf(v.y);
        v.z = roundtf(v.z); v.w = roundtf(v.w);
        p[i] = v;
    }
}

__global__ void cvtcopy_kernel(const float4* __restrict__ src, float4* __restrict__ dst, int n4)
{
    int i = blockIdx.x * blockDim.x + threadIdx.x;
    if (i < n4) {
        float4 v = src[i];
        v.x = roundtf(v.x); v.y = roundtf(v.y);
        v.z = roundtf(v.z); v.w = roundtf(v.w);
        dst[i] = v;
    }
}

// ---------------- small kernels ----------------
__global__ void embed_kernel(const int* __restrict__ tok, const float* __restrict__ emb,
                             float* __restrict__ x, float* __restrict__ xt)
{
    int idx = blockIdx.x * blockDim.x + threadIdx.x;
    int row = idx >> 7, c = idx & 127;
    int t = tok[row];
    float4 v = ((const float4*)emb)[((size_t)t << 7) + c];
    ((float4*)x)[((size_t)row << 7) + c] = v;
    v.x = roundtf(v.x); v.y = roundtf(v.y); v.z = roundtf(v.z); v.w = roundtf(v.w);
    ((float4*)xt)[((size_t)row << 7) + c] = v;
}

__global__ void pe_kernel(float* __restrict__ pe)
{
    int idx = blockIdx.x * blockDim.x + threadIdx.x;
    int j = idx >> 9, d = idx & 511;
    int k = d & 255;
    float inv = expf(-(float)k * (9.210340371976184f / 256.0f));
    float t = (float)(NN - 1 - j);
    float a = t * inv;
    pe[idx] = roundtf((d < 256) ? sinf(a) : cosf(a));
}

__global__ void transpose_pos_kernel(const float* __restrict__ pos, float* __restrict__ posT)
{
    int idx = blockIdx.x * blockDim.x + threadIdx.x;
    int l = idx >> 16;
    int d = (idx >> 10) & 63;
    int r = idx & 1023;
    posT[idx] = pos[(l << 16) + r * DHh + d];
}

__global__ void exps_all_kernel(const float* __restrict__ mems, const int* __restrict__ tms,
                                const float* __restrict__ Wexp, const float* __restrict__ bexp,
                                float* __restrict__ em_all, float* __restrict__ aux)
{
    int w = (blockIdx.x * blockDim.x + threadIdx.x) >> 5;
    int lane = threadIdx.x & 31;
    int l = w >> 11;
    int rem = w & 2047;
    int b = rem >> 10;
    const float* mr = mems + (size_t)w * DD;
    const float* we = Wexp + (size_t)l * DD;
    float s = 0.f;
    for (int d = lane; d < DD; d += 32) s += mr[d] * we[d];
#pragma unroll
    for (int o = 16; o > 0; o >>= 1) s += __shfl_down_sync(0xffffffffu, s, o);
    if (lane == 0) {
        float val = s + bexp[l];
        float sig = 1.f / (1.f + expf(-val));
        float ex = sig * 1024.0f;
        float t = (float)tms[w];
        float emv = fminf(fmaxf((ex - t) * (1.f / 128.f) + 1.f, 0.f), 1.f);
        em_all[w] = emv;
        if (emv > 0.f && emv < 1.f)
            atomicAdd(&aux[b], ex * (1.f / (128.f * 1024.f)));
    }
}

__global__ void zero_aux_kernel(float* __restrict__ aux)
{
    if (threadIdx.x < BB) aux[threadIdx.x] = 0.f;
}

__global__ void aux_out_kernel(const float* __restrict__ aux, float* __restrict__ out)
{
    if (threadIdx.x < BB) out[threadIdx.x] = aux[threadIdx.x];
}

// ---------------- flash attention, tf32 tensor cores ----------------
__global__ void __launch_bounds__(256, 1) fattn_kernel(
    const float* __restrict__ qkv, const float* __restrict__ memkv,
    const float* __restrict__ P, const float* __restrict__ em,
    float* __restrict__ out)
{
    extern __shared__ unsigned smu[];
    unsigned* Kts = smu;
    unsigned* Vt  = smu + 8704;
    unsigned* Pr  = smu + 17152;
    unsigned* Qs  = Pr;
    float*    ems = (float*)(smu + 34048);

    const int qt = blockIdx.x;
    const int h  = blockIdx.y;
    const int b  = blockIdx.z;
    const int tid = threadIdx.x;
    const int w = tid >> 5, lane = tid & 31, g = lane >> 2, tg = lane & 3;
    const int rA = w * 16 + g;
    const int rB = rA + 8;

    const unsigned smem_b = (unsigned)__cvta_generic_to_shared(smu);
    const unsigned prFragBase = smem_b + 17152u * 4u
        + (unsigned)((w * 16 + (lane & 15)) * 132) * 4u + (unsigned)(lane >> 4) * 16u;

    for (int j = tid; j < MM; j += 256) ems[j] = em[b * MM + j];

    {
        int row = tid >> 1, ch = (tid & 1) * 32;
        const float* qp = qkv + ((size_t)(b * NN) + qt * 128 + row) * QKVW + h * 64 + ch;
#pragma unroll
        for (int j4 = 0; j4 < 8; j4++) {
            float4 v = *(const float4*)(qp + j4 * 4);
            unsigned* dst = &Qs[row * 68 + ch + j4 * 4];
            dst[0] = f2tf32(v.x); dst[1] = f2tf32(v.y);
            dst[2] = f2tf32(v.z); dst[3] = f2tf32(v.w);
        }
    }
    __syncthreads();

    unsigned aq[8][4];
#pragma unroll
    for (int ks = 0; ks < 8; ks++) {
        aq[ks][0] = Qs[rA * 68 + ks * 8 + tg];
        aq[ks][1] = Qs[rB * 68 + ks * 8 + tg];
        aq[ks][2] = Qs[rA * 68 + ks * 8 + tg + 4];
        aq[ks][3] = Qs[rB * 68 + ks * 8 + tg + 4];
    }

    const int iA = qt * 128 + rA;
    const int iB = iA + 8;
    const float* ProwA = P + ((size_t)((b * HH + h) * NN + iA)) * NN + (NN - 1 - iA);
    const float* ProwB = P + ((size_t)((b * HH + h) * NN + iB)) * NN + (NN - 1 - iB);

    float mA = -1e30f, mB = -1e30f, lA = 0.f, lB = 0.f;
    float oacc[8][4];
#pragma unroll
    for (int nt = 0; nt < 8; nt++)
#pragma unroll
        for (int r = 0; r < 4; r++) oacc[nt][r] = 0.f;

    const int nkt = 8 + qt + 1;
    for (int kt = 0; kt < nkt; kt++) {
        __syncthreads();
        const bool isMem = (kt < 8);
        if (tid < 128) {
            int key = kt * 128 + tid;
            const float* kp = isMem
                ? memkv + ((size_t)(b * MM) + key) * (2 * DD) + h * 64
                : qkv + ((size_t)(b * NN) + (key - MM)) * QKVW + DD + h * 64;
#pragma unroll
            for (int j4 = 0; j4 < 16; j4++) {
                float4 v = *(const float4*)(kp + j4 * 4);
                int c = j4 * 4;
                Kts[(c + 0) * 136 + tid] = f2tf32(v.x);
                Kts[(c + 1) * 136 + tid] = f2tf32(v.y);
                Kts[(c + 2) * 136 + tid] = f2tf32(v.z);
                Kts[(c + 3) * 136 + tid] = f2tf32(v.w);
            }
        } else {
            int key = kt * 128 + tid - 128;
            const float* vp = isMem
                ? memkv + ((size_t)(b * MM) + key) * (2 * DD) + DD + h * 64
                : qkv + ((size_t)(b * NN) + (key - MM)) * QKVW + 2 * DD + h * 64;
#pragma unroll
            for (int j4 = 0; j4 < 16; j4++) {
                float4 v = *(const float4*)(vp + j4 * 4);
                int c = j4 * 4;
                Vt[(c + 0) * 132 + (tid - 128)] = f2tf32(v.x);
                Vt[(c + 1) * 132 + (tid - 128)] = f2tf32(v.y);
                Vt[(c + 2) * 132 + (tid - 128)] = f2tf32(v.z);
                Vt[(c + 3) * 132 + (tid - 128)] = f2tf32(v.w);
            }
        }
        __syncthreads();

        float s[16][4];
#pragma unroll
        for (int nt = 0; nt < 16; nt++)
            s[nt][0] = s[nt][1] = s[nt][2] = s[nt][3] = 0.f;
#pragma unroll
        for (int ks = 0; ks < 8; ks++) {
#pragma unroll
            for (int nt = 0; nt < 16; nt++) {
                unsigned bf[2];
                bf[0] = Kts[(ks * 8 + tg) * 136 + nt * 8 + g];
                bf[1] = Kts[(ks * 8 + tg + 4) * 136 + nt * 8 + g];
                mma_tf32(s[nt], aq[ks], bf);
            }
        }

        const bool isDiag = (kt == 8 + qt);
        float tmA = -1e30f, tmB = -1e30f;
        if (!isMem) {
            const int jjb = (kt - 8) * 128;
#pragma unroll
            for (int nt = 0; nt < 16; nt++) {
                int cl = nt * 8 + 2 * tg;
                int jj0 = jjb + cl;
                float pd0A = (!isDiag || cl     <= rA) ? ProwA[jj0]     : 0.f;
                float pd1A = (!isDiag || cl + 1 <= rA) ? ProwA[jj0 + 1] : 0.f;
                float pd0B = (!isDiag || cl     <= rB) ? ProwB[jj0]     : 0.f;
                float pd1B = (!isDiag || cl + 1 <= rB) ? ProwB[jj0 + 1] : 0.f;
                s[nt][0] = (s[nt][0] + pd0A) * 0.125f;
                s[nt][1] = (s[nt][1] + pd1A) * 0.125f;
                s[nt][2] = (s[nt][2] + pd0B) * 0.125f;
                s[nt][3] = (s[nt][3] + pd1B) * 0.125f;
                if (isDiag) {
                    if (cl     > rA) s[nt][0] = -1e30f;
                    if (cl + 1 > rA) s[nt][1] = -1e30f;
                    if (cl     > rB) s[nt][2] = -1e30f;
                    if (cl + 1 > rB) s[nt][3] = -1e30f;
                }
                tmA = fmaxf(tmA, fmaxf(s[nt][0], s[nt][1]));
                tmB = fmaxf(tmB, fmaxf(s[nt][2], s[nt][3]));
            }
        } else {
#pragma unroll
            for (int nt = 0; nt < 16; nt++) {
                s[nt][0] *= 0.125f; s[nt][1] *= 0.125f;
                s[nt][2] *= 0.125f; s[nt][3] *= 0.125f;
                tmA = fmaxf(tmA, fmaxf(s[nt][0], s[nt][1]));
                tmB = fmaxf(tmB, fmaxf(s[nt][2], s[nt][3]));
            }
        }
        tmA = fmaxf(tmA, __shfl_xor_sync(0xffffffffu, tmA, 1));
        tmA = fmaxf(tmA, __shfl_xor_sync(0xffffffffu, tmA, 2));
        tmB = fmaxf(tmB, __shfl_xor_sync(0xffffffffu, tmB, 1));
        tmB = fmaxf(tmB, __shfl_xor_sync(0xffffffffu, tmB, 2));

        float nmA = fmaxf(mA, tmA), nmB = fmaxf(mB, tmB);
        float aAl = __expf(mA - nmA), aBl = __expf(mB - nmB);
        mA = nmA; mB = nmB;
        lA *= aAl; lB *= aBl;
#pragma unroll
        for (int nt = 0; nt < 8; nt++) {
            oacc[nt][0] *= aAl; oacc[nt][1] *= aAl;
            oacc[nt][2] *= aBl; oacc[nt][3] *= aBl;
        }

        float ssA = 0.f, ssB = 0.f;
#pragma unroll
        for (int nt = 0; nt < 16; nt++) {
            float p0 = __expf(s[nt][0] - nmA), p1 = __expf(s[nt][1] - nmA);
            float p2 = __expf(s[nt][2] - nmB), p3 = __expf(s[nt][3] - nmB);
            ssA += p0 + p1; ssB += p2 + p3;
            int cbase = nt * 8 + 2 * tg;
            if (isMem) {
                float e0 = ems[kt * 128 + cbase], e1 = ems[kt * 128 + cbase + 1];
                p0 *= e0; p1 *= e1; p2 *= e0; p3 *= e1;
            }
            Pr[rA * 132 + cbase]     = f2tf32(p0);
            Pr[rA * 132 + cbase + 1] = f2tf32(p1);
            Pr[rB * 132 + cbase]     = f2tf32(p2);
            Pr[rB * 132 + cbase + 1] = f2tf32(p3);
        }
        ssA += __shfl_xor_sync(0xffffffffu, ssA, 1);
        ssA += __shfl_xor_sync(0xffffffffu, ssA, 2);
        ssB += __shfl_xor_sync(0xffffffffu, ssB, 1);
        ssB += __shfl_xor_sync(0xffffffffu, ssB, 2);
        lA += ssA; lB += ssB;
        __syncwarp();

#pragma unroll
        for (int ks = 0; ks < 16; ks++) {
            unsigned a[4];
            ldsm_x4(a, prFragBase + (unsigned)(ks * 32));
#pragma unroll
            for (int nt = 0; nt < 8; nt++) {
                unsigned bf[2];
                bf[0] = Vt[(nt * 8 + g) * 132 + ks * 8 + tg];
                bf[1] = Vt[(nt * 8 + g) * 132 + ks * 8 + tg + 4];
                mma_tf32(oacc[nt], a, bf);
            }
        }
    }

    float ivA = 1.f / lA, ivB = 1.f / lB;
    size_t orowA = ((size_t)(b * NN) + qt * 128 + rA) * DD + h * 64;
    size_t orowB = orowA + (size_t)8 * DD;
#pragma unroll
    for (int nt = 0; nt < 8; nt++) {
        int c = nt * 8 + 2 * tg;
        *(float2*)(out + orowA + c) =
            make_float2(roundtf(oacc[nt][0] * ivA), roundtf(oacc[nt][1] * ivA));
        *(float2*)(out + orowB + c) =
            make_float2(roundtf(oacc[nt][2] * ivB), roundtf(oacc[nt][3] * ivB));
    }
}

// ---------------- final LayerNorm (reads exact fp32 x, writes rounded xn) -------
__global__ void ln_kernel(const float* __restrict__ x, const float* __restrict__ g,
                          const float* __restrict__ b, float* __restrict__ y)
{
    int row = blockIdx.x, tid = threadIdx.x;
    __shared__ float rs[256], rq[256];
    const float* xr = x + (size_t)row * DD;
    float v0 = xr[tid], v1 = xr[tid + 256];
    rs[tid] = v0 + v1;
    rq[tid] = v0 * v0 + v1 * v1;
    __syncthreads();
    for (int s2 = 128; s2 > 0; s2 >>= 1) {
        if (tid < s2) { rs[tid] += rs[tid + s2]; rq[tid] += rq[tid + s2]; }
        __syncthreads();
    }
    float mu = rs[0] * (1.f / DD);
    float var = rq[0] * (1.f / DD) - mu * mu;
    float inv = 1.f / sqrtf(var + 1e-5f);
    float* yr = y + (size_t)row * DD;
    yr[tid] = roundtf((v0 - mu) * inv * g[tid] + b[tid]);
    yr[tid + 256] = roundtf((v1 - mu) * inv * g[tid + 256] + b[tid + 256]);
}

// ---------------- host ----------------
#define SMEM128 ((2 * 128 * 36 + 2 * 32 * 136) * 4)
#define SMEM64  ((2 * 64 * 36 + 2 * 32 * 136) * 4)
#define NOSPLIT (1 << 30)

static void gemmF(const float* A, const float* B1, const float* B2, int nsplit,
                  int ldb1, int ldb2, const float* bias, const float* bias2,
                  const float* res, float* C, float* Ct, int M, int N, int K, int lda,
                  long sA, long sA2, long sB2, long sBias2, long sC, long sC2,
                  int zH, int Z, int act, int rnd)
{
    int gx = (N + 127) / 128;
    if (gx * (M / 128) * Z >= 120) {
        dim3 grid(gx, M / 128, Z);
        gemm_tc_kernel<4><<<grid, 256, SMEM128>>>(A, B1, B2, nsplit, ldb1, ldb2,
            bias, bias2, res, C, Ct, M, N, K, lda, sA, sA2, sB2, sBias2, sC, sC2, zH, act, rnd);
    } else {
        dim3 grid(gx, M / 64, Z);
        gemm_tc_kernel<2><<<grid, 256, SMEM64>>>(A, B1, B2, nsplit, ldb1, ldb2,
            bias, bias2, res, C, Ct, M, N, K, lda, sA, sA2, sB2, sBias2, sC, sC2, zH, act, rnd);
    }
}

static void gemm(const float* A, const float* Bw, const float* bias, const float* res,
                 float* C, float* Ct, int M, int N, int K, int lda, long sA, long sC,
                 int Z, int act, int rnd)
{
    gemmF(A, Bw, 0, NOSPLIT, N, 0, bias, 0, res, C, Ct, M, N, K, lda,
          sA, 0, 0, 0, sC, 0, 1, Z, act, rnd);
}

static void cvt_inplace(const float* p, size_t n)
{
    cvt4_kernel<<<(unsigned)((n / 4 + 255) / 256), 256>>>((float4*)p, (int)(n / 4));
}

extern "C" void kernel_launch(void* const* d_in, const int* in_sizes, int n_in,
                              void* d_out, int out_size)
{
    const int*   tokens  = (const int*)d_in[0];
    const float* mems    = (const float*)d_in[1];
    const int*   times   = (const int*)d_in[2];
    const float* tok_emb = (const float*)d_in[3];
    const float* Wq      = (const float*)d_in[4];
    const float* bq      = (const float*)d_in[5];
    const float* Wkv     = (const float*)d_in[6];
    const float* bkv     = (const float*)d_in[7];
    const float* Wo      = (const float*)d_in[8];
    const float* bo      = (const float*)d_in[9];
    const float* Wpos    = (const float*)d_in[10];
    const float* bpos    = (const float*)d_in[11];
    const float* Wexp    = (const float*)d_in[12];
    const float* bexp    = (const float*)d_in[13];
    const float* W1      = (const float*)d_in[14];
    const float* b1      = (const float*)d_in[15];
    const float* W2      = (const float*)d_in[16];
    const float* b2      = (const float*)d_in[17];
    const float* ln_g    = (const float*)d_in[18];
    const float* ln_b    = (const float*)d_in[19];
    const float* Whead   = (const float*)d_in[20];
    float* out = (float*)d_out;

    float *x, *xt, *memt, *qkv, *memkv, *att, *h1, *xn, *pe, *pos, *posT, *P, *em, *aux;
    cudaGetSymbolAddress((void**)&x,     g_x);
    cudaGetSymbolAddress((void**)&xt,    g_xt);
    cudaGetSymbolAddress((void**)&memt,  g_memt);
    cudaGetSymbolAddress((void**)&qkv,   g_qkv);
    cudaGetSymbolAddress((void**)&memkv, g_memkv);
    cudaGetSymbolAddress((void**)&att,   g_att);
    cudaGetSymbolAddress((void**)&h1,    g_h1);
    cudaGetSymbolAddress((void**)&xn,    g_xn);
    cudaGetSymbolAddress((void**)&pe,    g_pe);
    cudaGetSymbolAddress((void**)&pos,   g_pos_all);
    cudaGetSymbolAddress((void**)&posT,  g_posT_all);
    cudaGetSymbolAddress((void**)&P,     g_P);
    cudaGetSymbolAddress((void**)&em,    g_em_all);
    cudaGetSymbolAddress((void**)&aux,   g_aux);

    cudaFuncSetAttribute(fattn_kernel, cudaFuncAttributeMaxDynamicSharedMemorySize, 140288);
    cudaFuncSetAttribute(gemm_tc_kernel<4>, cudaFuncAttributeMaxDynamicSharedMemorySize, SMEM128);
    cudaFuncSetAttribute(gemm_tc_kernel<2>, cudaFuncAttributeMaxDynamicSharedMemorySize, SMEM64);

    // pre-round WEIGHTS in place (B operands; idempotent)
    cvt_inplace(Wq,    (size_t)DEPTHL * DD * DD);
    cvt_inplace(Wkv,   (size_t)DEPTHL * DD * 2 * DD);
    cvt_inplace(Wo,    (size_t)DEPTHL * DD * DD);
    cvt_inplace(Wpos,  (size_t)DEPTHL * DD * DHh);
    cvt_inplace(W1,    (size_t)DEPTHL * DD * FF);
    cvt_inplace(W2,    (size_t)DEPTHL * FF * DD);
    cvt_inplace(Whead, (size_t)DD * VV);
    // rounded COPY of mems (raw mems stays fp32 for exps/aux)
    cvtcopy_kernel<<<(DEPTHL * BB * MM * DD / 4 + 255) / 256, 256>>>(
        (const float4*)mems, (float4*)memt, DEPTHL * BB * MM * DD / 4);

    pe_kernel<<<NN * DD / 256, 256>>>(pe);
    embed_kernel<<<BB * NN * 128 / 256, 256>>>(tokens, tok_emb, x, xt);
    zero_aux_kernel<<<1, 32>>>(aux);

    for (int l = 0; l < DEPTHL; l++) {
        // fused qkv = xt @ [Wq | Wkv] + [bq | bkv], rounded output
        gemmF(xt, Wq + (size_t)l * DD * DD, Wkv + (size_t)l * DD * 2 * DD, DD,
              DD, 2 * DD, bq + (size_t)l * DD, bkv + (size_t)l * 2 * DD, 0,
              qkv, 0, BB * NN, QKVW, DD, DD, 0, 0, 0, 0, 0, 0, 1, 1, 0, 1);
        if (l == 0) {
            exps_all_kernel<<<DEPTHL * BB * MM * 32 / 256, 256>>>(mems, times, Wexp, bexp, em, aux);
            gemmF(pe, Wpos, 0, NOSPLIT, DHh, 0, bpos, 0, 0, pos, 0,
                  NN, DHh, DD, DD, 0, 0, (long)DD * DHh, DHh, 0, (long)NN * DHh,
                  DEPTHL, DEPTHL, 0, 1);
            transpose_pos_kernel<<<DEPTHL * DHh * NN / 256, 256>>>(pos, posT);
        }
        // memory kv (A = rounded memt), rounded output
        gemm(memt + (size_t)l * BB * MM * DD, Wkv + (size_t)l * DD * 2 * DD,
             bkv + (size_t)l * 2 * DD, 0, memkv, 0, MM, 2 * DD, DD, DD,
             (long)MM * DD, (long)MM * 2 * DD, BB, 0, 1);
        // P[b,h] = Q[b,:,h] @ posT_l (fp32 out, scalar consumer)
        gemmF(qkv, posT + (size_t)l * DHh * NN, 0, NOSPLIT, NN, 0, 0, 0, 0, P, 0,
              NN, NN, DHh, QKVW, (long)NN * QKVW, 64, 0, 0,
              (long)HH * NN * NN, (long)NN * NN, HH, BB * HH, 0, 0);
        // attention (writes rounded att)
        fattn_kernel<<<dim3(NN / 128, HH, BB), 256, 140288>>>(
            qkv, memkv, P, em + (size_t)l * BB * MM, att);
        // x = x + att @ Wo + bo ; xt = round(x)
        gemm(att, Wo + (size_t)l * DD * DD, bo + (size_t)l * DD, x,
             x, xt, BB * NN, DD, DD, DD, 0, 0, 1, 0, 0);
        // h1 = gelu(xt @ W1 + b1), rounded
        gemm(xt, W1 + (size_t)l * DD * FF, b1 + (size_t)l * FF, 0,
             h1, 0, BB * NN, FF, DD, DD, 0, 0, 1, 1, 1);
        // x = x + h1 @ W2 + b2 ; xt = round(x)
        gemm(h1, W2 + (size_t)l * FF * DD, b2 + (size_t)l * DD, x,
             x, xt, BB * NN, DD, FF, FF, 0, 0, 1, 0, 0);
    }

    ln_kernel<<<BB * NN, 256>>>(x, ln_g, ln_b, xn);
    gemm(xn, Whead, 0, 0, out, 0, BB * NN, VV, DD, DD, 0, 0, 1, 0, 0);

    if (out_size == BB * NN * VV + BB)
        aux_out_kernel<<<1, 32>>>(aux, out + (size_t)BB * NN * VV);
}

// round 14
// speedup vs baseline: 1.2852x; 1.2852x over previous
#include <cuda_runtime.h>
#include <math.h>

#define BB 2
#define NN 1024
#define MM 1024
#define DD 512
#define HH 8
#define DHh 64
#define DEPTHL 4
#define VV 32000
#define FF 2048
#define MN (MM + NN)
#define QKVW 1536

// ---------------- scratch (static device globals; no allocation) ----------------
__device__ float g_x[BB * NN * DD];       // residual stream, exact fp32
__device__ float g_xt[BB * NN * DD];      // tf32-rounded shadow of x (GEMM A input)
__device__ float g_memt[DEPTHL * BB * MM * DD];  // tf32-rounded copy of mems
__device__ float g_qkv[BB * NN * QKVW];   // rounded
__device__ float g_memkv4[DEPTHL * BB * MM * 2 * DD];  // rounded, all layers
__device__ float g_att[BB * NN * DD];     // rounded
__device__ float g_h1[BB * NN * FF];      // rounded
__device__ float g_xn[BB * NN * DD];      // rounded
__device__ float g_pe[NN * DD];           // rounded
__device__ float g_pos_all[DEPTHL * NN * DHh];   // rounded
__device__ float g_posT_all[DEPTHL * DHh * NN];
__device__ float g_P[BB * HH * NN * NN];
__device__ float g_em_all[DEPTHL * BB * MM];
__device__ float g_aux[BB];

// ---------------- tf32 helpers ----------------
__device__ __forceinline__ unsigned f2tf32(float x) {
    unsigned u;
    asm("cvt.rna.tf32.f32 %0, %1;" : "=r"(u) : "f"(x));
    return u;
}
__device__ __forceinline__ float roundtf(float x) { return __uint_as_float(f2tf32(x)); }

__device__ __forceinline__ void mma_tf32(float* c, const unsigned* a, const unsigned* b) {
    asm volatile(
        "mma.sync.aligned.m16n8k8.row.col.f32.tf32.tf32.f32 "
        "{%0,%1,%2,%3}, {%4,%5,%6,%7}, {%8,%9}, {%0,%1,%2,%3};\n"
        : "+f"(c[0]), "+f"(c[1]), "+f"(c[2]), "+f"(c[3])
        : "r"(a[0]), "r"(a[1]), "r"(a[2]), "r"(a[3]), "r"(b[0]), "r"(b[1]));
}

__device__ __forceinline__ void ldsm_x4(unsigned* r, unsigned saddr) {
    asm volatile("ldmatrix.sync.aligned.m8n8.x4.shared.b16 {%0,%1,%2,%3}, [%4];"
        : "=r"(r[0]), "=r"(r[1]), "=r"(r[2]), "=r"(r[3]) : "r"(saddr));
}

__device__ __forceinline__ void cp16(unsigned dst, const float* src, unsigned sz) {
    asm volatile("cp.async.ca.shared.global [%0], [%1], 16, %2;"
        :: "r"(dst), "l"(src), "r"(sz));
}
__device__ __forceinline__ void cp_commit() { asm volatile("cp.async.commit_group;"); }
template<int Nn> __device__ __forceinline__ void cp_wait() {
    asm volatile("cp.async.wait_group %0;" :: "n"(Nn));
}

// ---------------- tf32 GEMM: cp.async for BOTH operands (pre-rounded in gmem) ----
// C[M,N] = act(A[M,K] @ B[K,N] + bias) + res.  TMI: M-tile = 32*TMI, N-tile 128.
// smem: As[2][TM][36] + Bs[2][32][136]. Global A and B MUST hold tf32 values.
// Ct (optional): second output, tf32-rounded (same layout/strides as C).
template<int TMI>
__global__ void __launch_bounds__(256, 2) gemm_tc_kernel(
    const float* __restrict__ A, const float* __restrict__ Bw,
    const float* __restrict__ Bw2, int nsplit, int ldb1, int ldb2,
    const float* __restrict__ bias, const float* __restrict__ bias2,
    const float* __restrict__ res, float* __restrict__ C, float* __restrict__ Ct,
    int M, int N, int K, int lda,
    long sA, long sA2, long sB2, long sBias2, long sC, long sC2,
    int zH, int doGelu, int doRound)
{
    constexpr int TM = 32 * TMI;
    constexpr int ASTG = TM * 36;
    constexpr int BSTG = 32 * 136;
    extern __shared__ unsigned smu[];

    int zb = blockIdx.z / zH, zh = blockIdx.z % zH;
    A += (long)zb * sA + (long)zh * sA2;
    Bw += (long)zh * sB2;
    if (bias) bias += (long)zh * sBias2;
    C += (long)zb * sC + (long)zh * sC2;
    if (Ct) Ct += (long)zb * sC + (long)zh * sC2;
    const float* resb = res ? (res + (long)zb * sC + (long)zh * sC2) : (const float*)0;

    const int tid = threadIdx.x;
    const int lane = tid & 31;
    const int warp = tid >> 5;
    const int m0 = blockIdx.y * TM;
    const int n0 = blockIdx.x * 128;
    const int wm = (warp >> 2) * (TM / 2);
    const int wn = (warp & 3) * 32;
    const int g = lane >> 2;
    const int tg = lane & 3;

    const float* Bu; const float* biasu; int ldb, nloc;
    if (n0 >= nsplit) { Bu = Bw2; biasu = bias2; ldb = ldb2; nloc = n0 - nsplit; }
    else             { Bu = Bw;  biasu = bias;  ldb = ldb1; nloc = n0; }

    const int arow = tid >> 3;
    const int acol = (tid & 7) << 2;
    const int brow = tid >> 5;
    const int bcol = (tid & 31) << 2;

    const float* Aptr = A + (long)(m0 + arow) * lda + acol;
    const float* Bbase = Bu + nloc + bcol;
    const bool bOK = (n0 + bcol + 4) <= N;
    const unsigned bsz = bOK ? 16u : 0u;

    float acc[TMI][4][4];
#pragma unroll
    for (int mi = 0; mi < TMI; mi++)
#pragma unroll
        for (int ni = 0; ni < 4; ni++)
#pragma unroll
            for (int r = 0; r < 4; r++) acc[mi][ni][r] = 0.f;

    const int chunks = K >> 5;

    unsigned smem_b = (unsigned)__cvta_generic_to_shared(smu);
    const unsigned aDst = smem_b + (unsigned)(arow * 36 + acol) * 4u;
    const unsigned bDst = smem_b + (unsigned)(2 * ASTG) * 4u
                                 + (unsigned)(brow * 136 + bcol) * 4u;
    const unsigned aFragBase = smem_b + (unsigned)((wm + (lane & 15)) * 36) * 4u
                                      + (unsigned)(lane >> 4) * 16u;

    // prologue: chunk 0 into buf 0
    {
#pragma unroll
        for (int i = 0; i < TMI; i++)
            cp16(aDst + (unsigned)(i * 32 * 36) * 4u, Aptr + (long)i * 32 * lda, 16u);
#pragma unroll
        for (int i = 0; i < 4; i++)
            cp16(bDst + (unsigned)(i * 8 * 136) * 4u,
                 bOK ? Bbase + (long)(brow + i * 8) * ldb : Bu, bsz);
        cp_commit();
        cp_wait<0>();
        __syncthreads();
    }

    for (int c = 0; c < chunks; c++) {
        const int buf = c & 1;
        const unsigned aBufBase = aFragBase + (unsigned)buf * (ASTG * 4);
        const unsigned* Bs = smu + 2 * ASTG + buf * BSTG;
        const bool more = (c + 1 < chunks);

        if (more) {
            int k0 = (c + 1) << 5;
            unsigned ad = aDst + (unsigned)((buf ^ 1) * ASTG) * 4u;
#pragma unroll
            for (int i = 0; i < TMI; i++)
                cp16(ad + (unsigned)(i * 32 * 36) * 4u, Aptr + (long)i * 32 * lda + k0, 16u);
            unsigned bd = bDst + (unsigned)((buf ^ 1) * BSTG) * 4u;
#pragma unroll
            for (int i = 0; i < 4; i++)
                cp16(bd + (unsigned)(i * 8 * 136) * 4u,
                     bOK ? Bbase + (long)(k0 + brow + i * 8) * ldb : Bu, bsz);
            cp_commit();
        }

#pragma unroll
        for (int kk = 0; kk < 4; kk++) {
            int ko = kk << 3;
            unsigned af[TMI][4];
#pragma unroll
            for (int mi = 0; mi < TMI; mi++)
                ldsm_x4(af[mi], aBufBase + (unsigned)(mi * (16 * 36 * 4) + kk * 32));
            unsigned bf[4][2];
#pragma unroll
            for (int ni = 0; ni < 4; ni++) {
                int cN = wn + ni * 8 + g;
                bf[ni][0] = Bs[(ko + tg) * 136 + cN];
                bf[ni][1] = Bs[(ko + tg + 4) * 136 + cN];
            }
#pragma unroll
            for (int mi = 0; mi < TMI; mi++)
#pragma unroll
                for (int ni = 0; ni < 4; ni++)
                    mma_tf32(acc[mi][ni], af[mi], bf[ni]);
        }

        cp_wait<0>();
        __syncthreads();
    }

    const int biasOff = nloc - n0;
#pragma unroll
    for (int mi = 0; mi < TMI; mi++) {
        int gm0 = m0 + wm + mi * 16 + g;
#pragma unroll
        for (int ni = 0; ni < 4; ni++) {
            int gn = n0 + wn + ni * 8 + 2 * tg;
            if (gn >= N) continue;
            float bsum0 = biasu ? biasu[gn + biasOff] : 0.f;
            float bsum1 = biasu ? biasu[gn + biasOff + 1] : 0.f;
#pragma unroll
            for (int half = 0; half < 2; half++) {
                int gm = gm0 + half * 8;
                float v0 = acc[mi][ni][half * 2 + 0] + bsum0;
                float v1 = acc[mi][ni][half * 2 + 1] + bsum1;
                if (doGelu) {
                    v0 = 0.5f * v0 * (1.0f + erff(v0 * 0.7071067811865476f));
                    v1 = 0.5f * v1 * (1.0f + erff(v1 * 0.7071067811865476f));
                }
                if (resb) {
                    const float2 r2 = *(const float2*)(resb + (long)gm * N + gn);
                    v0 += r2.x; v1 += r2.y;
                }
                if (doRound) { v0 = roundtf(v0); v1 = roundtf(v1); }
                *(float2*)(C + (long)gm * N + gn) = make_float2(v0, v1);
                if (Ct)
                    *(float2*)(Ct + (long)gm * N + gn) =
                        make_float2(roundtf(v0), roundtf(v1));
            }
        }
    }
}

// ---------------- fused in-place tf32 rounding of ALL weights (one launch) -------
#define CW0 (DEPTHL * DD * DD / 4)            // Wq
#define CW1 (CW0 + DEPTHL * DD * 2 * DD / 4)  // +Wkv
#define CW2 (CW1 + DEPTHL * DD * DD / 4)      // +Wo
#define CW3 (CW2 + DEPTHL * DD * DHh / 4)     // +Wpos
#define CW4 (CW3 + DEPTHL * DD * FF / 4)      // +W1
#define CW5 (CW4 + DEPTHL * FF * DD / 4)      // +W2
#define CW6 (CW5 + DD * VV / 4)               // +Whead
__global__ void cvt_all_kernel(float4* wq, float4* wkv, float4* wo, float4* wpos,
                               float4* w1, float4* w2, float4* whead)
{
    int i = blockIdx.x * blockDim.x + threadIdx.x;
    if (i >= CW6) return;
    float4* p;
    if      (i < CW0) p = wq + i;
    else if (i < CW1) p = wkv + (i - CW0);
    else if (i < CW2) p = wo + (i - CW1);
    else if (i < CW3) p = wpos + (i - CW2);
    else if (i < CW4) p = w1 + (i - CW3);
    else if (i < CW5) p = w2 + (i - CW4);
    else              p = whead + (i - CW5);
    float4 v = *p;
    v.x = roundtf(v.x); v.y = roundtf(v.y);
    v.z = roundtf(v.z); v.w = roundtf(v.w);
    *p = v;
}

__global__ void cvtcopy_kernel(const float4* __restrict__ src, float4* __restrict__ dst, int n4)
{
    int i = blockIdx.x * blockDim.x + threadIdx.x;
    if (i < n4) {
        float4 v = src[i];
        v.x = roundtf(v.x); v.y = roundtf(v.y);
        v.z = roundtf(v.z); v.w = roundtf(v.w);
        dst[i] = v;
    }
}

// ---------------- small kernels ----------------
__global__ void embed_kernel(const int* __restrict__ tok, const float* __restrict__ emb,
                             float* __restrict__ x, float* __restrict__ xt)
{
    int idx = blockIdx.x * blockDim.x + threadIdx.x;
    int row = idx >> 7, c = idx & 127;
    int t = tok[row];
    float4 v = ((const float4*)emb)[((size_t)t << 7) + c];
    ((float4*)x)[((size_t)row << 7) + c] = v;
    v.x = roundtf(v.x); v.y = roundtf(v.y); v.z = roundtf(v.z); v.w = roundtf(v.w);
    ((float4*)xt)[((size_t)row << 7) + c] = v;
}

__global__ void pe_kernel(float* __restrict__ pe)
{
    int idx = blockIdx.x * blockDim.x + threadIdx.x;
    int j = idx >> 9, d = idx & 511;
    int k = d & 255;
    float inv = expf(-(float)k * (9.210340371976184f / 256.0f));
    float t = (float)(NN - 1 - j);
    float a = t * inv;
    pe[idx] = roundtf((d < 256) ? sinf(a) : cosf(a));
}

__global__ void transpose_pos_kernel(const float* __restrict__ pos, float* __restrict__ posT)
{
    int idx = blockIdx.x * blockDim.x + threadIdx.x;
    int l = idx >> 16;
    int d = (idx >> 10) & 63;
    int r = idx & 1023;
    posT[idx] = pos[(l << 16) + r * DHh + d];
}

__global__ void exps_all_kernel(const float* __restrict__ mems, const int* __restrict__ tms,
                                const float* __restrict__ Wexp, const float* __restrict__ bexp,
                                float* __restrict__ em_all, float* __restrict__ aux)
{
    int w = (blockIdx.x * blockDim.x + threadIdx.x) >> 5;
    int lane = threadIdx.x & 31;
    int l = w >> 11;
    int rem = w & 2047;
    int b = rem >> 10;
    const float* mr = mems + (size_t)w * DD;
    const float* we = Wexp + (size_t)l * DD;
    float s = 0.f;
    for (int d = lane; d < DD; d += 32) s += mr[d] * we[d];
#pragma unroll
    for (int o = 16; o > 0; o >>= 1) s += __shfl_down_sync(0xffffffffu, s, o);
    if (lane == 0) {
        float val = s + bexp[l];
        float sig = 1.f / (1.f + expf(-val));
        float ex = sig * 1024.0f;
        float t = (float)tms[w];
        float emv = fminf(fmaxf((ex - t) * (1.f / 128.f) + 1.f, 0.f), 1.f);
        em_all[w] = emv;
        if (emv > 0.f && emv < 1.f)
            atomicAdd(&aux[b], ex * (1.f / (128.f * 1024.f)));
    }
}

__global__ void zero_aux_kernel(float* __restrict__ aux)
{
    if (threadIdx.x < BB) aux[threadIdx.x] = 0.f;
}

__global__ void aux_out_kernel(const float* __restrict__ aux, float* __restrict__ out)
{
    if (threadIdx.x < BB) out[threadIdx.x] = aux[threadIdx.x];
}

// ---------------- flash attention, tf32 tensor cores ----------------
__global__ void __launch_bounds__(256, 1) fattn_kernel(
    const float* __restrict__ qkv, const float* __restrict__ memkv,
    const float* __restrict__ P, const float* __restrict__ em,
    float* __restrict__ out)
{
    extern __shared__ unsigned smu[];
    unsigned* Kts = smu;
    unsigned* Vt  = smu + 8704;
    unsigned* Pr  = smu + 17152;
    unsigned* Qs  = Pr;
    float*    ems = (float*)(smu + 34048);

    const int qt = blockIdx.x;
    const int h  = blockIdx.y;
    const int b  = blockIdx.z;
    const int tid = threadIdx.x;
    const int w = tid >> 5, lane = tid & 31, g = lane >> 2, tg = lane & 3;
    const int rA = w * 16 + g;
    const int rB = rA + 8;

    const unsigned smem_b = (unsigned)__cvta_generic_to_shared(smu);
    const unsigned prFragBase = smem_b + 17152u * 4u
        + (unsigned)((w * 16 + (lane & 15)) * 132) * 4u + (unsigned)(lane >> 4) * 16u;

    for (int j = tid; j < MM; j += 256) ems[j] = em[b * MM + j];

    {
        int row = tid >> 1, ch = (tid & 1) * 32;
        const float* qp = qkv + ((size_t)(b * NN) + qt * 128 + row) * QKVW + h * 64 + ch;
#pragma unroll
        for (int j4 = 0; j4 < 8; j4++) {
            float4 v = *(const float4*)(qp + j4 * 4);
            unsigned* dst = &Qs[row * 68 + ch + j4 * 4];
            dst[0] = f2tf32(v.x); dst[1] = f2tf32(v.y);
            dst[2] = f2tf32(v.z); dst[3] = f2tf32(v.w);
        }
    }
    __syncthreads();

    unsigned aq[8][4];
#pragma unroll
    for (int ks = 0; ks < 8; ks++) {
        aq[ks][0] = Qs[rA * 68 + ks * 8 + tg];
        aq[ks][1] = Qs[rB * 68 + ks * 8 + tg];
        aq[ks][2] = Qs[rA * 68 + ks * 8 + tg + 4];
        aq[ks][3] = Qs[rB * 68 + ks * 8 + tg + 4];
    }

    const int iA = qt * 128 + rA;
    const int iB = iA + 8;
    const float* ProwA = P + ((size_t)((b * HH + h) * NN + iA)) * NN + (NN - 1 - iA);
    const float* ProwB = P + ((size_t)((b * HH + h) * NN + iB)) * NN + (NN - 1 - iB);

    float mA = -1e30f, mB = -1e30f, lA = 0.f, lB = 0.f;
    float oacc[8][4];
#pragma unroll
    for (int nt = 0; nt < 8; nt++)
#pragma unroll
        for (int r = 0; r < 4; r++) oacc[nt][r] = 0.f;

    const int nkt = 8 + qt + 1;
    for (int kt = 0; kt < nkt; kt++) {
        __syncthreads();
        const bool isMem = (kt < 8);
        if (tid < 128) {
            int key = kt * 128 + tid;
            const float* kp = isMem
                ? memkv + ((size_t)(b * MM) + key) * (2 * DD) + h * 64
                : qkv + ((size_t)(b * NN) + (key - MM)) * QKVW + DD + h * 64;
#pragma unroll
            for (int j4 = 0; j4 < 16; j4++) {
                float4 v = *(const float4*)(kp + j4 * 4);
                int c = j4 * 4;
                Kts[(c + 0) * 136 + tid] = f2tf32(v.x);
                Kts[(c + 1) * 136 + tid] = f2tf32(v.y);
                Kts[(c + 2) * 136 + tid] = f2tf32(v.z);
                Kts[(c + 3) * 136 + tid] = f2tf32(v.w);
            }
        } else {
            int key = kt * 128 + tid - 128;
            const float* vp = isMem
                ? memkv + ((size_t)(b * MM) + key) * (2 * DD) + DD + h * 64
                : qkv + ((size_t)(b * NN) + (key - MM)) * QKVW + 2 * DD + h * 64;
#pragma unroll
            for (int j4 = 0; j4 < 16; j4++) {
                float4 v = *(const float4*)(vp + j4 * 4);
                int c = j4 * 4;
                Vt[(c + 0) * 132 + (tid - 128)] = f2tf32(v.x);
                Vt[(c + 1) * 132 + (tid - 128)] = f2tf32(v.y);
                Vt[(c + 2) * 132 + (tid - 128)] = f2tf32(v.z);
                Vt[(c + 3) * 132 + (tid - 128)] = f2tf32(v.w);
            }
        }
        __syncthreads();

        float s[16][4];
#pragma unroll
        for (int nt = 0; nt < 16; nt++)
            s[nt][0] = s[nt][1] = s[nt][2] = s[nt][3] = 0.f;
#pragma unroll
        for (int ks = 0; ks < 8; ks++) {
#pragma unroll
            for (int nt = 0; nt < 16; nt++) {
                unsigned bf[2];
                bf[0] = Kts[(ks * 8 + tg) * 136 + nt * 8 + g];
                bf[1] = Kts[(ks * 8 + tg + 4) * 136 + nt * 8 + g];
                mma_tf32(s[nt], aq[ks], bf);
            }
        }

        const bool isDiag = (kt == 8 + qt);
        float tmA = -1e30f, tmB = -1e30f;
        if (!isMem) {
            const int jjb = (kt - 8) * 128;
#pragma unroll
            for (int nt = 0; nt < 16; nt++) {
                int cl = nt * 8 + 2 * tg;
                int jj0 = jjb + cl;
                float pd0A = (!isDiag || cl     <= rA) ? ProwA[jj0]     : 0.f;
                float pd1A = (!isDiag || cl + 1 <= rA) ? ProwA[jj0 + 1] : 0.f;
                float pd0B = (!isDiag || cl     <= rB) ? ProwB[jj0]     : 0.f;
                float pd1B = (!isDiag || cl + 1 <= rB) ? ProwB[jj0 + 1] : 0.f;
                s[nt][0] = (s[nt][0] + pd0A) * 0.125f;
                s[nt][1] = (s[nt][1] + pd1A) * 0.125f;
                s[nt][2] = (s[nt][2] + pd0B) * 0.125f;
                s[nt][3] = (s[nt][3] + pd1B) * 0.125f;
                if (isDiag) {
                    if (cl     > rA) s[nt][0] = -1e30f;
                    if (cl + 1 > rA) s[nt][1] = -1e30f;
                    if (cl     > rB) s[nt][2] = -1e30f;
                    if (cl + 1 > rB) s[nt][3] = -1e30f;
                }
                tmA = fmaxf(tmA, fmaxf(s[nt][0], s[nt][1]));
                tmB = fmaxf(tmB, fmaxf(s[nt][2], s[nt][3]));
            }
        } else {
#pragma unroll
            for (int nt = 0; nt < 16; nt++) {
                s[nt][0] *= 0.125f; s[nt][1] *= 0.125f;
                s[nt][2] *= 0.125f; s[nt][3] *= 0.125f;
                tmA = fmaxf(tmA, fmaxf(s[nt][0], s[nt][1]));
                tmB = fmaxf(tmB, fmaxf(s[nt][2], s[nt][3]));
            }
        }
        tmA = fmaxf(tmA, __shfl_xor_sync(0xffffffffu, tmA, 1));
        tmA = fmaxf(tmA, __shfl_xor_sync(0xffffffffu, tmA, 2));
        tmB = fmaxf(tmB, __shfl_xor_sync(0xffffffffu, tmB, 1));
        tmB = fmaxf(tmB, __shfl_xor_sync(0xffffffffu, tmB, 2));

        float nmA = fmaxf(mA, tmA), nmB = fmaxf(mB, tmB);
        float aAl = __expf(mA - nmA), aBl = __expf(mB - nmB);
        mA = nmA; mB = nmB;
        lA *= aAl; lB *= aBl;
#pragma unroll
        for (int nt = 0; nt < 8; nt++) {
            oacc[nt][0] *= aAl; oacc[nt][1] *= aAl;
            oacc[nt][2] *= aBl; oacc[nt][3] *= aBl;
        }

        float ssA = 0.f, ssB = 0.f;
#pragma unroll
        for (int nt = 0; nt < 16; nt++) {
            float p0 = __expf(s[nt][0] - nmA), p1 = __expf(s[nt][1] - nmA);
            float p2 = __expf(s[nt][2] - nmB), p3 = __expf(s[nt][3] - nmB);
            ssA += p0 + p1; ssB += p2 + p3;
            int cbase = nt * 8 + 2 * tg;
            if (isMem) {
                float e0 = ems[kt * 128 + cbase], e1 = ems[kt * 128 + cbase + 1];
                p0 *= e0; p1 *= e1; p2 *= e0; p3 *= e1;
            }
            Pr[rA * 132 + cbase]     = f2tf32(p0);
            Pr[rA * 132 + cbase + 1] = f2tf32(p1);
            Pr[rB * 132 + cbase]     = f2tf32(p2);
            Pr[rB * 132 + cbase + 1] = f2tf32(p3);
        }
        ssA += __shfl_xor_sync(0xffffffffu, ssA, 1);
        ssA += __shfl_xor_sync(0xffffffffu, ssA, 2);
        ssB += __shfl_xor_sync(0xffffffffu, ssB, 1);
        ssB += __shfl_xor_sync(0xffffffffu, ssB, 2);
        lA += ssA; lB += ssB;
        __syncwarp();

#pragma unroll
        for (int ks = 0; ks < 16; ks++) {
            unsigned a[4];
            ldsm_x4(a, prFragBase + (unsigned)(ks * 32));
#pragma unroll
            for (int nt = 0; nt < 8; nt++) {
                unsigned bf[2];
                bf[0] = Vt[(nt * 8 + g) * 132 + ks * 8 + tg];
                bf[1] = Vt[(nt * 8 + g) * 132 + ks * 8 + tg + 4];
                mma_tf32(oacc[nt], a, bf);
            }
        }
    }

    float ivA = 1.f / lA, ivB = 1.f / lB;
    size_t orowA = ((size_t)(b * NN) + qt * 128 + rA) * DD + h * 64;
    size_t orowB = orowA + (size_t)8 * DD;
#pragma unroll
    for (int nt = 0; nt < 8; nt++) {
        int c = nt * 8 + 2 * tg;
        *(float2*)(out + orowA + c) =
            make_float2(roundtf(oacc[nt][0] * ivA), roundtf(oacc[nt][1] * ivA));
        *(float2*)(out + orowB + c) =
            make_float2(roundtf(oacc[nt][2] * ivB), roundtf(oacc[nt][3] * ivB));
    }
}

// ---------------- final LayerNorm ----------------
__global__ void ln_kernel(const float* __restrict__ x, const float* __restrict__ g,
                          const float* __restrict__ b, float* __restrict__ y)
{
    int row = blockIdx.x, tid = threadIdx.x;
    __shared__ float rs[256], rq[256];
    const float* xr = x + (size_t)row * DD;
    float v0 = xr[tid], v1 = xr[tid + 256];
    rs[tid] = v0 + v1;
    rq[tid] = v0 * v0 + v1 * v1;
    __syncthreads();
    for (int s2 = 128; s2 > 0; s2 >>= 1) {
        if (tid < s2) { rs[tid] += rs[tid + s2]; rq[tid] += rq[tid + s2]; }
        __syncthreads();
    }
    float mu = rs[0] * (1.f / DD);
    float var = rq[0] * (1.f / DD) - mu * mu;
    float inv = 1.f / sqrtf(var + 1e-5f);
    float* yr = y + (size_t)row * DD;
    yr[tid] = roundtf((v0 - mu) * inv * g[tid] + b[tid]);
    yr[tid + 256] = roundtf((v1 - mu) * inv * g[tid + 256] + b[tid + 256]);
}

// ---------------- host ----------------
#define SMEM128 ((2 * 128 * 36 + 2 * 32 * 136) * 4)
#define SMEM64  ((2 * 64 * 36 + 2 * 32 * 136) * 4)
#define NOSPLIT (1 << 30)

static void gemmF(const float* A, const float* B1, const float* B2, int nsplit,
                  int ldb1, int ldb2, const float* bias, const float* bias2,
                  const float* res, float* C, float* Ct, int M, int N, int K, int lda,
                  long sA, long sA2, long sB2, long sBias2, long sC, long sC2,
                  int zH, int Z, int act, int rnd)
{
    int gx = (N + 127) / 128;
    if (gx * (M / 128) * Z >= 120) {
        dim3 grid(gx, M / 128, Z);
        gemm_tc_kernel<4><<<grid, 256, SMEM128>>>(A, B1, B2, nsplit, ldb1, ldb2,
            bias, bias2, res, C, Ct, M, N, K, lda, sA, sA2, sB2, sBias2, sC, sC2, zH, act, rnd);
    } else {
        dim3 grid(gx, M / 64, Z);
        gemm_tc_kernel<2><<<grid, 256, SMEM64>>>(A, B1, B2, nsplit, ldb1, ldb2,
            bias, bias2, res, C, Ct, M, N, K, lda, sA, sA2, sB2, sBias2, sC, sC2, zH, act, rnd);
    }
}

static void gemm(const float* A, const float* Bw, const float* bias, const float* res,
                 float* C, float* Ct, int M, int N, int K, int lda, long sA, long sC,
                 int Z, int act, int rnd)
{
    gemmF(A, Bw, 0, NOSPLIT, N, 0, bias, 0, res, C, Ct, M, N, K, lda,
          sA, 0, 0, 0, sC, 0, 1, Z, act, rnd);
}

extern "C" void kernel_launch(void* const* d_in, const int* in_sizes, int n_in,
                              void* d_out, int out_size)
{
    const int*   tokens  = (const int*)d_in[0];
    const float* mems    = (const float*)d_in[1];
    const int*   times   = (const int*)d_in[2];
    const float* tok_emb = (const float*)d_in[3];
    const float* Wq      = (const float*)d_in[4];
    const float* bq      = (const float*)d_in[5];
    const float* Wkv     = (const float*)d_in[6];
    const float* bkv     = (const float*)d_in[7];
    const float* Wo      = (const float*)d_in[8];
    const float* bo      = (const float*)d_in[9];
    const float* Wpos    = (const float*)d_in[10];
    const float* bpos    = (const float*)d_in[11];
    const float* Wexp    = (const float*)d_in[12];
    const float* bexp    = (const float*)d_in[13];
    const float* W1      = (const float*)d_in[14];
    const float* b1      = (const float*)d_in[15];
    const float* W2      = (const float*)d_in[16];
    const float* b2      = (const float*)d_in[17];
    const float* ln_g    = (const float*)d_in[18];
    const float* ln_b    = (const float*)d_in[19];
    const float* Whead   = (const float*)d_in[20];
    float* out = (float*)d_out;

    float *x, *xt, *memt, *qkv, *memkv4, *att, *h1, *xn, *pe, *pos, *posT, *P, *em, *aux;
    cudaGetSymbolAddress((void**)&x,      g_x);
    cudaGetSymbolAddress((void**)&xt,     g_xt);
    cudaGetSymbolAddress((void**)&memt,   g_memt);
    cudaGetSymbolAddress((void**)&qkv,    g_qkv);
    cudaGetSymbolAddress((void**)&memkv4, g_memkv4);
    cudaGetSymbolAddress((void**)&att,    g_att);
    cudaGetSymbolAddress((void**)&h1,     g_h1);
    cudaGetSymbolAddress((void**)&xn,     g_xn);
    cudaGetSymbolAddress((void**)&pe,     g_pe);
    cudaGetSymbolAddress((void**)&pos,    g_pos_all);
    cudaGetSymbolAddress((void**)&posT,   g_posT_all);
    cudaGetSymbolAddress((void**)&P,      g_P);
    cudaGetSymbolAddress((void**)&em,     g_em_all);
    cudaGetSymbolAddress((void**)&aux,    g_aux);

    cudaFuncSetAttribute(fattn_kernel, cudaFuncAttributeMaxDynamicSharedMemorySize, 140288);
    cudaFuncSetAttribute(gemm_tc_kernel<4>, cudaFuncAttributeMaxDynamicSharedMemorySize, SMEM128);
    cudaFuncSetAttribute(gemm_tc_kernel<2>, cudaFuncAttributeMaxDynamicSharedMemorySize, SMEM64);

    // launch 0: round ALL weights in place (idempotent)
    cvt_all_kernel<<<(CW6 + 255) / 256, 256>>>(
        (float4*)Wq, (float4*)Wkv, (float4*)Wo, (float4*)Wpos,
        (float4*)W1, (float4*)W2, (float4*)Whead);
    // launch 1: rounded COPY of mems (raw mems stays fp32 for exps/aux)
    cvtcopy_kernel<<<(DEPTHL * BB * MM * DD / 4 + 255) / 256, 256>>>(
        (const float4*)mems, (float4*)memt, DEPTHL * BB * MM * DD / 4);
    // launches 2-4
    pe_kernel<<<NN * DD / 256, 256>>>(pe);
    embed_kernel<<<BB * NN * 128 / 256, 256>>>(tokens, tok_emb, x, xt);
    zero_aux_kernel<<<1, 32>>>(aux);

    for (int l = 0; l < DEPTHL; l++) {
        // launch 5 on l==0: fused qkv GEMM -> ncu capture slot
        gemmF(xt, Wq + (size_t)l * DD * DD, Wkv + (size_t)l * DD * 2 * DD, DD,
              DD, 2 * DD, bq + (size_t)l * DD, bkv + (size_t)l * 2 * DD, 0,
              qkv, 0, BB * NN, QKVW, DD, DD, 0, 0, 0, 0, 0, 0, 1, 1, 0, 1);
        if (l == 0) {
            exps_all_kernel<<<DEPTHL * BB * MM * 32 / 256, 256>>>(mems, times, Wexp, bexp, em, aux);
            gemmF(pe, Wpos, 0, NOSPLIT, DHh, 0, bpos, 0, 0, pos, 0,
                  NN, DHh, DD, DD, 0, 0, (long)DD * DHh, DHh, 0, (long)NN * DHh,
                  DEPTHL, DEPTHL, 0, 1);
            transpose_pos_kernel<<<DEPTHL * DHh * NN / 256, 256>>>(pos, posT);
            // batched memkv for ALL layers: z = b*DEPTHL + l
            gemmF(memt, Wkv, 0, NOSPLIT, 2 * DD, 0, bkv, 0, 0, memkv4, 0,
                  MM, 2 * DD, DD, DD,
                  (long)MM * DD, (long)BB * MM * DD,          // A: zb=b, zh=l
                  (long)DD * 2 * DD, 2 * DD,                  // B,bias: zh=l
                  (long)MM * 2 * DD, (long)BB * MM * 2 * DD,  // C: zb=b, zh=l
                  DEPTHL, BB * DEPTHL, 0, 1);
        }
        // P[b,h] = Q[b,:,h] @ posT_l (fp32 out, scalar consumer)
        gemmF(qkv, posT + (size_t)l * DHh * NN, 0, NOSPLIT, NN, 0, 0, 0, 0, P, 0,
              NN, NN, DHh, QKVW, (long)NN * QKVW, 64, 0, 0,
              (long)HH * NN * NN, (long)NN * NN, HH, BB * HH, 0, 0);
        // attention (writes rounded att)
        fattn_kernel<<<dim3(NN / 128, HH, BB), 256, 140288>>>(
            qkv, memkv4 + (size_t)l * BB * MM * 2 * DD, P,
            em + (size_t)l * BB * MM, att);
        // x = x + att @ Wo + bo ; xt = round(x)
        gemm(att, Wo + (size_t)l * DD * DD, bo + (size_t)l * DD, x,
             x, xt, BB * NN, DD, DD, DD, 0, 0, 1, 0, 0);
        // h1 = gelu(xt @ W1 + b1), rounded
        gemm(xt, W1 + (size_t)l * DD * FF, b1 + (size_t)l * FF, 0,
             h1, 0, BB * NN, FF, DD, DD, 0, 0, 1, 1, 1);
        // x = x + h1 @ W2 + b2 ; xt = round(x)
        gemm(h1, W2 + (size_t)l * FF * DD, b2 + (size_t)l * DD, x,
             x, xt, BB * NN, DD, FF, FF, 0, 0, 1, 0, 0);
    }

    ln_kernel<<<BB * NN, 256>>>(x, ln_g, ln_b, xn);
    gemm(xn, Whead, 0, 0, out, 0, BB * NN, VV, DD, DD, 0, 0, 1, 0, 0);

    if (out_size == BB * NN * VV + BB)
        aux_out_kernel<<<1, 32>>>(aux, out + (size_t)BB * NN * VV);
}